// round 1
// baseline (speedup 1.0000x reference)
#include <cuda_runtime.h>
#include <math.h>

#define BM 128
#define BK 16
#define NTHREADS 256
#define HDIM 64
#define QN 4

// ---------------- quantum gate helpers (compile-time masks) ----------------
template <int MASK>
__device__ __forceinline__ void ry_gate(float (&re)[16], float (&im)[16], float c, float s) {
#pragma unroll
    for (int idx = 0; idx < 16; idx++) {
        if ((idx & MASK) == 0) {
            const int j = idx | MASK;
            float r0 = re[idx], i0 = im[idx];
            float r1 = re[j],   i1 = im[j];
            re[idx] = c * r0 - s * r1;
            im[idx] = c * i0 - s * i1;
            re[j]   = s * r0 + c * r1;
            im[j]   = s * i0 + c * i1;
        }
    }
}

template <int MASK>
__device__ __forceinline__ void rz_gate(float (&re)[16], float (&im)[16], float c, float s) {
#pragma unroll
    for (int idx = 0; idx < 16; idx++) {
        // bit==0: multiply by (c - i s); bit==1: multiply by (c + i s)
        float sgn = (idx & MASK) ? s : -s;
        float r = re[idx], i = im[idx];
        re[idx] = r * c - i * sgn;
        im[idx] = i * c + r * sgn;
    }
}

template <int CM, int TM>
__device__ __forceinline__ void cnot_gate(float (&re)[16], float (&im)[16]) {
#pragma unroll
    for (int idx = 0; idx < 16; idx++) {
        if ((idx & CM) && !(idx & TM)) {
            const int j = idx | TM;
            float tr = re[idx]; re[idx] = re[j]; re[j] = tr;
            float ti = im[idx]; im[idx] = im[j]; im[j] = ti;
        }
    }
}

__device__ __forceinline__ void quantum_var_layer(float (&re)[16], float (&im)[16],
                                                  const float* qc, const float* qs, int base) {
    // wire i -> bit (3-i): masks 8,4,2,1. param index = base + i*2 + p
    ry_gate<8>(re, im, qc[base + 0], qs[base + 0]);
    rz_gate<8>(re, im, qc[base + 1], qs[base + 1]);
    ry_gate<4>(re, im, qc[base + 2], qs[base + 2]);
    rz_gate<4>(re, im, qc[base + 3], qs[base + 3]);
    ry_gate<2>(re, im, qc[base + 4], qs[base + 4]);
    rz_gate<2>(re, im, qc[base + 5], qs[base + 5]);
    ry_gate<1>(re, im, qc[base + 6], qs[base + 6]);
    rz_gate<1>(re, im, qc[base + 7], qs[base + 7]);
    // CNOT ring: (0,1),(1,2),(2,3),(3,0) in wire numbering -> bit masks
    cnot_gate<8, 4>(re, im);
    cnot_gate<4, 2>(re, im);
    cnot_gate<2, 1>(re, im);
    cnot_gate<1, 8>(re, im);
}

// ---------------- fused kernel ----------------
__global__ __launch_bounds__(NTHREADS, 2)
void qh_fused_kernel(const float* __restrict__ x,  const float* __restrict__ W1,
                     const float* __restrict__ b1, const float* __restrict__ bn_g,
                     const float* __restrict__ bn_b, const float* __restrict__ bn_m,
                     const float* __restrict__ bn_v, const float* __restrict__ W2,
                     const float* __restrict__ b2, const float* __restrict__ qw,
                     const float* __restrict__ W3, const float* __restrict__ b3,
                     float* __restrict__ out, int B, int K, int C) {
    __shared__ union {
        struct { float As[BK * 132]; float Bs[BK * 68]; } t;   // GEMM tiles
        float Hs[BM * 65];                                     // H tile (post BN)
    } u;
    __shared__ float s_scale[HDIM], s_shift[HDIM], s_b1[HDIM];
    __shared__ float s_w2[QN * HDIM], s_b2[QN];
    __shared__ float s_qwc[16], s_qws[16];
    __shared__ float s_w3[64], s_b3[16];

    const int tid = threadIdx.x;
    const int m0  = blockIdx.x * BM;

    // ---- one-time smem setup (covered by first __syncthreads in main loop)
    if (tid < HDIM) {
        float sc = bn_g[tid] * rsqrtf(bn_v[tid] + 1e-5f);
        s_scale[tid] = sc;
        s_shift[tid] = bn_b[tid] - bn_m[tid] * sc;
        s_b1[tid]    = b1[tid];
    }
    if (tid < QN * HDIM) s_w2[tid] = W2[tid];
    if (tid < QN)        s_b2[tid] = b2[tid];
    if (tid < 16) {
        float sv, cv;
        sincosf(0.5f * qw[tid], &sv, &cv);
        s_qwc[tid] = cv; s_qws[tid] = sv;
    }
    if (tid < C * QN) s_w3[tid] = W3[tid];
    if (tid < C)      s_b3[tid] = b3[tid];

    // ---- GEMM1: 128x64 tile, K-loop with register prefetch
    const int tx = tid & 15;          // 0..15 -> 4 cols each
    const int ty = tid >> 4;          // 0..15 -> 8 rows each
    const int lrow0 = tid >> 2;       // 0..63
    const int lrow1 = lrow0 + 64;     // 64..127
    const int lkq   = (tid & 3) * 4;  // k offset within chunk (0,4,8,12)
    const int wrow  = tid >> 2;       // W1 row 0..63

    float acc[8][4];
#pragma unroll
    for (int r = 0; r < 8; r++)
#pragma unroll
        for (int j = 0; j < 4; j++) acc[r][j] = 0.f;

    const float4 zero4 = make_float4(0.f, 0.f, 0.f, 0.f);
    float4 pa0, pa1, pb;

    // prefetch chunk 0
    {
        int gr0 = m0 + lrow0, gr1 = m0 + lrow1;
        pa0 = (gr0 < B) ? *(const float4*)(x + (size_t)gr0 * K + lkq) : zero4;
        pa1 = (gr1 < B) ? *(const float4*)(x + (size_t)gr1 * K + lkq) : zero4;
        pb  = *(const float4*)(W1 + (size_t)wrow * K + lkq);
    }

    for (int k0 = 0; k0 < K; k0 += BK) {
        __syncthreads();
        // store prefetched tiles (transposed: [k][m] / [k][n])
        u.t.As[(lkq + 0) * 132 + lrow0] = pa0.x;
        u.t.As[(lkq + 1) * 132 + lrow0] = pa0.y;
        u.t.As[(lkq + 2) * 132 + lrow0] = pa0.z;
        u.t.As[(lkq + 3) * 132 + lrow0] = pa0.w;
        u.t.As[(lkq + 0) * 132 + lrow1] = pa1.x;
        u.t.As[(lkq + 1) * 132 + lrow1] = pa1.y;
        u.t.As[(lkq + 2) * 132 + lrow1] = pa1.z;
        u.t.As[(lkq + 3) * 132 + lrow1] = pa1.w;
        u.t.Bs[(lkq + 0) * 68 + wrow] = pb.x;
        u.t.Bs[(lkq + 1) * 68 + wrow] = pb.y;
        u.t.Bs[(lkq + 2) * 68 + wrow] = pb.z;
        u.t.Bs[(lkq + 3) * 68 + wrow] = pb.w;
        __syncthreads();

        int kn = k0 + BK;
        if (kn < K) {  // prefetch next chunk (overlaps compute below)
            int gr0 = m0 + lrow0, gr1 = m0 + lrow1;
            pa0 = (gr0 < B) ? *(const float4*)(x + (size_t)gr0 * K + kn + lkq) : zero4;
            pa1 = (gr1 < B) ? *(const float4*)(x + (size_t)gr1 * K + kn + lkq) : zero4;
            pb  = *(const float4*)(W1 + (size_t)wrow * K + kn + lkq);
        }

#pragma unroll
        for (int kk = 0; kk < BK; kk++) {
            float4 a0 = *(const float4*)&u.t.As[kk * 132 + ty * 8];
            float4 a1 = *(const float4*)&u.t.As[kk * 132 + ty * 8 + 4];
            float4 b  = *(const float4*)&u.t.Bs[kk * 68 + tx * 4];
            float av[8] = {a0.x, a0.y, a0.z, a0.w, a1.x, a1.y, a1.z, a1.w};
            float bv[4] = {b.x, b.y, b.z, b.w};
#pragma unroll
            for (int r = 0; r < 8; r++)
#pragma unroll
                for (int j = 0; j < 4; j++) acc[r][j] = fmaf(av[r], bv[j], acc[r][j]);
        }
    }

    // ---- epilogue: bias + relu + BN into smem H tile
    __syncthreads();
#pragma unroll
    for (int r = 0; r < 8; r++) {
        int row = ty * 8 + r;
#pragma unroll
        for (int j = 0; j < 4; j++) {
            int col = tx * 4 + j;
            float v = acc[r][j] + s_b1[col];
            v = fmaxf(v, 0.f);
            v = v * s_scale[col] + s_shift[col];
            u.Hs[row * 65 + col] = v;
        }
    }
    __syncthreads();

    // ---- per-row: small GEMM + quantum sim + output GEMM (threads 0..127)
    if (tid < BM && (m0 + tid) < B) {
        const float* hr = &u.Hs[tid * 65];

        float cA[QN], sA[QN];
#pragma unroll
        for (int j = 0; j < QN; j++) {
            float d0 = 0.f, d1 = 0.f, d2 = 0.f, d3 = 0.f;
            const float* w = &s_w2[j * HDIM];
#pragma unroll
            for (int h = 0; h < HDIM; h += 4) {
                d0 = fmaf(hr[h + 0], w[h + 0], d0);
                d1 = fmaf(hr[h + 1], w[h + 1], d1);
                d2 = fmaf(hr[h + 2], w[h + 2], d2);
                d3 = fmaf(hr[h + 3], w[h + 3], d3);
            }
            float xq  = tanhf((d0 + d1) + (d2 + d3) + s_b2[j]);   // pre_quantum tanh
            float ang = tanhf(xq) * 3.14159265358979323846f;      // extra tanh in QuantumLayer
            sincosf(0.5f * ang, &sA[j], &cA[j]);
        }

        // initial product state after per-row RYs (real amplitudes)
        float re[16], im[16];
#pragma unroll
        for (int idx = 0; idx < 16; idx++) {
            float v = ((idx & 8) ? sA[0] : cA[0]) * ((idx & 4) ? sA[1] : cA[1]) *
                      ((idx & 2) ? sA[2] : cA[2]) * ((idx & 1) ? sA[3] : cA[3]);
            re[idx] = v;
            im[idx] = 0.f;
        }

        quantum_var_layer(re, im, s_qwc, s_qws, 0);
        quantum_var_layer(re, im, s_qwc, s_qws, 8);

        // Z expectations
        float p[16];
#pragma unroll
        for (int idx = 0; idx < 16; idx++) p[idx] = re[idx] * re[idx] + im[idx] * im[idx];
        float z[QN];
#pragma unroll
        for (int i = 0; i < QN; i++) {
            const int mask = 8 >> i;
            float acc_z = 0.f;
#pragma unroll
            for (int idx = 0; idx < 16; idx++) acc_z += (idx & mask) ? -p[idx] : p[idx];
            z[i] = acc_z;
        }

        // final classifier: out = z @ W3^T + b3
        float* orow = out + (size_t)(m0 + tid) * C;
        for (int c = 0; c < C; c++) {
            float o = s_b3[c];
#pragma unroll
            for (int j = 0; j < QN; j++) o = fmaf(z[j], s_w3[c * QN + j], o);
            orow[c] = o;
        }
    }
}

extern "C" void kernel_launch(void* const* d_in, const int* in_sizes, int n_in,
                              void* d_out, int out_size) {
    const float* x    = (const float*)d_in[0];
    const float* W1   = (const float*)d_in[1];
    const float* b1   = (const float*)d_in[2];
    const float* bn_g = (const float*)d_in[3];
    const float* bn_b = (const float*)d_in[4];
    const float* bn_m = (const float*)d_in[5];
    const float* bn_v = (const float*)d_in[6];
    const float* W2   = (const float*)d_in[7];
    const float* b2   = (const float*)d_in[8];
    const float* qw   = (const float*)d_in[9];
    const float* W3   = (const float*)d_in[10];
    const float* b3   = (const float*)d_in[11];

    const int Hn = in_sizes[2];           // 64
    const int K  = in_sizes[1] / Hn;      // 1280
    const int B  = in_sizes[0] / K;       // 32768
    const int C  = in_sizes[11];          // 10

    int grid = (B + BM - 1) / BM;
    qh_fused_kernel<<<grid, NTHREADS>>>(x, W1, b1, bn_g, bn_b, bn_m, bn_v,
                                        W2, b2, qw, W3, b3,
                                        (float*)d_out, B, K, C);
}

// round 5
// speedup vs baseline: 2.2286x; 2.2286x over previous
#include <cuda_runtime.h>
#include <cuda_bf16.h>
#include <math.h>
#include <stdint.h>

#define MT 128          // rows per CTA
#define NT 64           // N (H dim)
#define KC 64           // K elems per chunk
#define NTHREADS 256
#define QN 4
#define A_HI_OFF 0
#define A_LO_OFF 16384
#define B_HI_OFF 32768
#define B_LO_OFF 40960
#define STAGE_BYTES 49152
#define DSMEM_BYTES (STAGE_BYTES + 1024)

// ---------------- helpers ----------------
__device__ __forceinline__ uint32_t smem_u32(const void* p) {
    uint32_t a;
    asm("{ .reg .u64 t; cvta.to.shared.u64 t, %1; cvt.u32.u64 %0, t; }" : "=r"(a) : "l"(p));
    return a;
}
__device__ __forceinline__ void sts_v2(uint32_t addr, uint32_t a, uint32_t b) {
    asm volatile("st.shared.v2.u32 [%0], {%1, %2};" :: "r"(addr), "r"(a), "r"(b) : "memory");
}
__device__ __forceinline__ uint32_t cvt2bf(float hi, float lo) {
    uint32_t r;
    asm("cvt.rn.bf16x2.f32 %0, %1, %2;" : "=r"(r) : "f"(hi), "f"(lo));
    return r;
}
__device__ __forceinline__ void ldsm4(uint32_t* r, uint32_t addr) {
    asm volatile("ldmatrix.sync.aligned.m8n8.x4.shared.b16 {%0,%1,%2,%3}, [%4];"
                 : "=r"(r[0]), "=r"(r[1]), "=r"(r[2]), "=r"(r[3]) : "r"(addr));
}
__device__ __forceinline__ void mma16816(float* d, const uint32_t* a, const uint32_t* b) {
    asm volatile(
        "mma.sync.aligned.m16n8k16.row.col.f32.bf16.bf16.f32 "
        "{%0,%1,%2,%3}, {%4,%5,%6,%7}, {%8,%9}, {%0,%1,%2,%3};\n"
        : "+f"(d[0]), "+f"(d[1]), "+f"(d[2]), "+f"(d[3])
        : "r"(a[0]), "r"(a[1]), "r"(a[2]), "r"(a[3]), "r"(b[0]), "r"(b[1]));
}
__device__ __forceinline__ uint32_t sw128(uint32_t off) {
    return off ^ ((off >> 3) & 0x70u);
}

// ---------------- quantum gate helpers (compile-time masks) ----------------
template <int MASK>
__device__ __forceinline__ void ry_gate(float (&re)[16], float (&im)[16], float c, float s) {
#pragma unroll
    for (int idx = 0; idx < 16; idx++) {
        if ((idx & MASK) == 0) {
            const int j = idx | MASK;
            float r0 = re[idx], i0 = im[idx];
            float r1 = re[j],   i1 = im[j];
            re[idx] = c * r0 - s * r1;
            im[idx] = c * i0 - s * i1;
            re[j]   = s * r0 + c * r1;
            im[j]   = s * i0 + c * i1;
        }
    }
}
template <int MASK>
__device__ __forceinline__ void rz_gate(float (&re)[16], float (&im)[16], float c, float s) {
#pragma unroll
    for (int idx = 0; idx < 16; idx++) {
        float sgn = (idx & MASK) ? s : -s;
        float r = re[idx], i = im[idx];
        re[idx] = r * c - i * sgn;
        im[idx] = i * c + r * sgn;
    }
}
template <int CM, int TM>
__device__ __forceinline__ void cnot_gate(float (&re)[16], float (&im)[16]) {
#pragma unroll
    for (int idx = 0; idx < 16; idx++) {
        if ((idx & CM) && !(idx & TM)) {
            const int j = idx | TM;
            float tr = re[idx]; re[idx] = re[j]; re[j] = tr;
            float ti = im[idx]; im[idx] = im[j]; im[j] = ti;
        }
    }
}
__device__ __forceinline__ void quantum_var_layer(float (&re)[16], float (&im)[16],
                                                  const float* qc, const float* qs, int base) {
    ry_gate<8>(re, im, qc[base + 0], qs[base + 0]);
    rz_gate<8>(re, im, qc[base + 1], qs[base + 1]);
    ry_gate<4>(re, im, qc[base + 2], qs[base + 2]);
    rz_gate<4>(re, im, qc[base + 3], qs[base + 3]);
    ry_gate<2>(re, im, qc[base + 4], qs[base + 4]);
    rz_gate<2>(re, im, qc[base + 5], qs[base + 5]);
    ry_gate<1>(re, im, qc[base + 6], qs[base + 6]);
    rz_gate<1>(re, im, qc[base + 7], qs[base + 7]);
    cnot_gate<8, 4>(re, im);
    cnot_gate<4, 2>(re, im);
    cnot_gate<2, 1>(re, im);
    cnot_gate<1, 8>(re, im);
}

// ---------------- fused kernel ----------------
__global__ __launch_bounds__(NTHREADS, 2)
void qh_mma_kernel(const float* __restrict__ x,  const float* __restrict__ W1,
                   const float* __restrict__ b1, const float* __restrict__ bn_g,
                   const float* __restrict__ bn_b, const float* __restrict__ bn_m,
                   const float* __restrict__ bn_v, const float* __restrict__ W2,
                   const float* __restrict__ b2, const float* __restrict__ qw,
                   const float* __restrict__ W3, const float* __restrict__ b3,
                   float* __restrict__ out, int B, int K, int C) {
    extern __shared__ char dsm[];
    __shared__ float s_b1[NT], s_scale[NT], s_shift[NT];
    __shared__ float s_w2[QN * NT], s_b2[QN];
    __shared__ float s_qc[16], s_qs[16];
    __shared__ float s_w3[40], s_b3[16];

    const int tid  = threadIdx.x;
    const int wid  = tid >> 5;
    const int lane = tid & 31;
    const int m0   = blockIdx.x * MT;

    // dynamic smem, 1024-aligned base
    const uint32_t dsm_u32 = smem_u32(dsm);
    const uint32_t dbase   = (dsm_u32 + 1023u) & ~1023u;
    char* dbase_ptr = dsm + (dbase - dsm_u32);

    // ---- one-time smem constants
    if (tid < NT) {
        float sc = bn_g[tid] * rsqrtf(bn_v[tid] + 1e-5f);
        s_scale[tid] = sc;
        s_shift[tid] = bn_b[tid] - bn_m[tid] * sc;
        s_b1[tid]    = b1[tid];
    }
    s_w2[tid & (QN * NT - 1)] = W2[tid & (QN * NT - 1)];
    if (tid < QN) s_b2[tid] = b2[tid];
    if (tid < 16) {
        float sv, cv;
        sincosf(0.5f * qw[tid], &sv, &cv);
        s_qc[tid] = cv; s_qs[tid] = sv;
    }
    if (tid < C * QN) s_w3[tid] = W3[tid];
    if (tid < C)      s_b3[tid] = b3[tid];

    // warp tiling: 4 (M) x 2 (N); each warp does 32x32
    const int wm = wid & 3;
    const int wn = wid >> 2;

    // ldmatrix lane address components
    const int a_row = (lane & 7) + ((lane >> 3) & 1) * 8;     // row within 16
    const int a_kb  = ((lane >> 4) & 1) * 16;                 // k byte offset within 32B
    const int b_row = (lane & 7) + ((lane >> 4) & 1) * 8;     // n within 16
    const int b_kb  = ((lane >> 3) & 1) * 16;

    // producer indexing (same for all chunks)
    const int pr  = tid >> 4;            // 0..15 stride 16 -> row = pr + 16*i
    const int pcg = (tid & 15) << 2;     // fp32 col offset (4 floats)
    const int pcb = (tid & 15) << 3;     // byte offset in 128B bf16 row

    float acc[2][4][4];
#pragma unroll
    for (int m = 0; m < 2; m++)
#pragma unroll
        for (int n = 0; n < 4; n++)
#pragma unroll
            for (int q = 0; q < 4; q++) acc[m][n][q] = 0.f;

    const int nch = K / KC;  // 20
    float4 va[8], vb[4];

    // prefetch chunk 0
#pragma unroll
    for (int i = 0; i < 8; i++)
        va[i] = *(const float4*)(x + (size_t)(m0 + pr + 16 * i) * K + pcg);
#pragma unroll
    for (int i = 0; i < 4; i++)
        vb[i] = *(const float4*)(W1 + (size_t)(pr + 16 * i) * K + pcg);

    for (int c = 0; c < nch; c++) {
        // ---- convert + store (chunk c) into the single stage
#pragma unroll
        for (int i = 0; i < 8; i++) {
            uint32_t sw = sw128((uint32_t)((pr + 16 * i) * 128 + pcb));
            float4 v = va[i];
            uint32_t h01 = cvt2bf(v.y, v.x);
            uint32_t h23 = cvt2bf(v.w, v.z);
            float h0 = __uint_as_float(h01 << 16);
            float h1 = __uint_as_float(h01 & 0xffff0000u);
            float h2 = __uint_as_float(h23 << 16);
            float h3 = __uint_as_float(h23 & 0xffff0000u);
            uint32_t l01 = cvt2bf(v.y - h1, v.x - h0);
            uint32_t l23 = cvt2bf(v.w - h3, v.z - h2);
            sts_v2(dbase + A_HI_OFF + sw, h01, h23);
            sts_v2(dbase + A_LO_OFF + sw, l01, l23);
        }
#pragma unroll
        for (int i = 0; i < 4; i++) {
            uint32_t sw = sw128((uint32_t)((pr + 16 * i) * 128 + pcb));
            float4 v = vb[i];
            uint32_t h01 = cvt2bf(v.y, v.x);
            uint32_t h23 = cvt2bf(v.w, v.z);
            float h0 = __uint_as_float(h01 << 16);
            float h1 = __uint_as_float(h01 & 0xffff0000u);
            float h2 = __uint_as_float(h23 << 16);
            float h3 = __uint_as_float(h23 & 0xffff0000u);
            uint32_t l01 = cvt2bf(v.y - h1, v.x - h0);
            uint32_t l23 = cvt2bf(v.w - h3, v.z - h2);
            sts_v2(dbase + B_HI_OFF + sw, h01, h23);
            sts_v2(dbase + B_LO_OFF + sw, l01, l23);
        }
        __syncthreads();

        // ---- prefetch chunk c+1 (overlaps the mma section below)
        if (c + 1 < nch) {
            const int k0 = (c + 1) * KC;
#pragma unroll
            for (int i = 0; i < 8; i++)
                va[i] = *(const float4*)(x + (size_t)(m0 + pr + 16 * i) * K + k0 + pcg);
#pragma unroll
            for (int i = 0; i < 4; i++)
                vb[i] = *(const float4*)(W1 + (size_t)(pr + 16 * i) * K + k0 + pcg);
        }

        // ---- consume: ldmatrix + mma (3 passes: hh, lh, hl)
#pragma unroll
        for (int ks = 0; ks < 4; ks++) {
            const uint32_t kbyte = ks * 32;
            uint32_t Ah[2][4], Al[2][4], Bh[8], Bl[8];
#pragma unroll
            for (int m = 0; m < 2; m++) {
                uint32_t sw = sw128((uint32_t)((wm * 32 + m * 16 + a_row) * 128 + kbyte + a_kb));
                ldsm4(Ah[m], dbase + A_HI_OFF + sw);
                ldsm4(Al[m], dbase + A_LO_OFF + sw);
            }
#pragma unroll
            for (int p = 0; p < 2; p++) {
                uint32_t sw = sw128((uint32_t)((wn * 32 + p * 16 + b_row) * 128 + kbyte + b_kb));
                ldsm4(&Bh[p * 4], dbase + B_HI_OFF + sw);
                ldsm4(&Bl[p * 4], dbase + B_LO_OFF + sw);
            }
#pragma unroll
            for (int m = 0; m < 2; m++)
#pragma unroll
                for (int n = 0; n < 4; n++) {
                    const uint32_t* bh = &Bh[(n >> 1) * 4 + (n & 1) * 2];
                    const uint32_t* bl = &Bl[(n >> 1) * 4 + (n & 1) * 2];
                    mma16816(acc[m][n], Ah[m], bh);
                    mma16816(acc[m][n], Al[m], bh);
                    mma16816(acc[m][n], Ah[m], bl);
                }
        }
        __syncthreads();
    }

    // ---- fragments -> H smem (reuse stage memory), fusing bias+ReLU+BN
    float* Hs = (float*)dbase_ptr;   // 128 x 65 fp32
#pragma unroll
    for (int m = 0; m < 2; m++) {
        int row = wm * 32 + m * 16 + (lane >> 2);
#pragma unroll
        for (int n = 0; n < 4; n++) {
            int col = wn * 32 + n * 8 + (lane & 3) * 2;
#pragma unroll
            for (int q = 0; q < 4; q++) {
                int rr = row + (q >> 1) * 8;
                int cc = col + (q & 1);
                float v = acc[m][n][q] + s_b1[cc];
                v = fmaxf(v, 0.f);
                v = v * s_scale[cc] + s_shift[cc];
                Hs[rr * 65 + cc] = v;
            }
        }
    }
    __syncthreads();

    // ---- per-row: small GEMM + quantum sim + classifier (threads 0..127)
    if (tid < MT) {
        const float* hr = &Hs[tid * 65];

        float cA[QN], sA[QN];
#pragma unroll
        for (int j = 0; j < QN; j++) {
            float d0 = 0.f, d1 = 0.f, d2 = 0.f, d3 = 0.f;
            const float* w = &s_w2[j * NT];
#pragma unroll
            for (int h = 0; h < NT; h += 4) {
                d0 = fmaf(hr[h + 0], w[h + 0], d0);
                d1 = fmaf(hr[h + 1], w[h + 1], d1);
                d2 = fmaf(hr[h + 2], w[h + 2], d2);
                d3 = fmaf(hr[h + 3], w[h + 3], d3);
            }
            float xq  = tanhf((d0 + d1) + (d2 + d3) + s_b2[j]);   // pre_quantum tanh
            float ang = tanhf(xq) * 3.14159265358979323846f;      // extra tanh in QuantumLayer
            sincosf(0.5f * ang, &sA[j], &cA[j]);
        }

        float re[16], im[16];
#pragma unroll
        for (int idx = 0; idx < 16; idx++) {
            float v = ((idx & 8) ? sA[0] : cA[0]) * ((idx & 4) ? sA[1] : cA[1]) *
                      ((idx & 2) ? sA[2] : cA[2]) * ((idx & 1) ? sA[3] : cA[3]);
            re[idx] = v;
            im[idx] = 0.f;
        }
        quantum_var_layer(re, im, s_qc, s_qs, 0);
        quantum_var_layer(re, im, s_qc, s_qs, 8);

        float p[16];
#pragma unroll
        for (int idx = 0; idx < 16; idx++) p[idx] = re[idx] * re[idx] + im[idx] * im[idx];
        float z[QN];
#pragma unroll
        for (int i = 0; i < QN; i++) {
            const int mask = 8 >> i;
            float acc_z = 0.f;
#pragma unroll
            for (int idx = 0; idx < 16; idx++) acc_z += (idx & mask) ? -p[idx] : p[idx];
            z[i] = acc_z;
        }

        float* orow = out + (size_t)(m0 + tid) * C;
        for (int cc = 0; cc < C; cc++) {
            float o = s_b3[cc];
#pragma unroll
            for (int j = 0; j < QN; j++) o = fmaf(z[j], s_w3[cc * QN + j], o);
            orow[cc] = o;
        }
    }
}

extern "C" void kernel_launch(void* const* d_in, const int* in_sizes, int n_in,
                              void* d_out, int out_size) {
    const float* x    = (const float*)d_in[0];
    const float* W1   = (const float*)d_in[1];
    const float* b1   = (const float*)d_in[2];
    const float* bn_g = (const float*)d_in[3];
    const float* bn_b = (const float*)d_in[4];
    const float* bn_m = (const float*)d_in[5];
    const float* bn_v = (const float*)d_in[6];
    const float* W2   = (const float*)d_in[7];
    const float* b2   = (const float*)d_in[8];
    const float* qw   = (const float*)d_in[9];
    const float* W3   = (const float*)d_in[10];
    const float* b3   = (const float*)d_in[11];

    const int Hn = in_sizes[2];           // 64
    const int K  = in_sizes[1] / Hn;      // 1280
    const int B  = in_sizes[0] / K;       // 32768
    const int C  = in_sizes[11];          // 10

    cudaFuncSetAttribute(qh_mma_kernel, cudaFuncAttributeMaxDynamicSharedMemorySize,
                         DSMEM_BYTES);

    int grid = B / MT;   // 256
    qh_mma_kernel<<<grid, NTHREADS, DSMEM_BYTES>>>(x, W1, b1, bn_g, bn_b, bn_m, bn_v,
                                                   W2, b2, qw, W3, b3,
                                                   (float*)d_out, B, K, C);
}